// round 2
// baseline (speedup 1.0000x reference)
#include <cuda_runtime.h>
#include <math.h>
#include <stdint.h>

#define FF  128     // frames
#define NP  300     // predictions per frame
#define MT  32      // targets per frame
#define KID 512     // id classes

__device__ double g_part[FF * 3];   // per-frame partials: l1, giou, nll

// ============================================================
// Fused kernel: cost matrix (shared) -> warp-level JV Hungarian
// -> per-frame loss partials. One block per frame, 1024 threads.
// ============================================================
__global__ void __launch_bounds__(1024, 1)
fused_kernel(const float* __restrict__ pl,
             const float* __restrict__ pb,
             const float* __restrict__ il,
             const int*   __restrict__ labels,
             const float* __restrict__ tbx,
             const int*   __restrict__ tids) {
    __shared__ float  s_cost[MT * NP];       // 38400 B  [m][n]
    __shared__ double s_v[NP + 1];           // 2408 B
    __shared__ double s_minv[NP + 1];        // 2408 B
    __shared__ double s_u[MT + 1];           // 264 B
    __shared__ short  s_p[NP + 1];           // 602 B
    __shared__ short  s_way[NP + 1];         // 602 B
    __shared__ unsigned char s_used[NP + 1]; // 301 B
    __shared__ int    s_pidx[MT];
    __shared__ float  s_tb[MT][4];
    __shared__ int    s_lab[MT];
    __shared__ float  s_l1[MT], s_g[MT], s_nll[MT];

    const int f   = blockIdx.x;
    const int tid = threadIdx.x;

    // ---- stage targets ----
    if (tid < MT) {
        s_lab[tid] = labels[f * MT + tid];
        #pragma unroll
        for (int c = 0; c < 4; ++c) s_tb[tid][c] = tbx[(f * MT + tid) * 4 + c];
    }
    __syncthreads();

    // ---- phase 1: cost matrix into shared ----
    for (int t = tid; t < MT * NP; t += 1024) {
        int m = t / NP, n = t - m * NP;
        float l0 = pl[(f * NP + n) * 2 + 0];
        float l1 = pl[(f * NP + n) * 2 + 1];
        float mx = fmaxf(l0, l1);
        float e0 = __expf(l0 - mx), e1 = __expf(l1 - mx);
        float inv = 1.0f / (e0 + e1);
        float p0 = e0 * inv, p1 = e1 * inv;
        float cx = pb[(f * NP + n) * 4 + 0];
        float cy = pb[(f * NP + n) * 4 + 1];
        float w  = pb[(f * NP + n) * 4 + 2];
        float h  = pb[(f * NP + n) * 4 + 3];
        float ax0 = cx - 0.5f * w, ay0 = cy - 0.5f * h;
        float ax1 = cx + 0.5f * w, ay1 = cy + 0.5f * h;
        float area1 = (ax1 - ax0) * (ay1 - ay0);

        float bcx = s_tb[m][0], bcy = s_tb[m][1], bw = s_tb[m][2], bh = s_tb[m][3];
        float bx0 = bcx - 0.5f * bw, by0 = bcy - 0.5f * bh;
        float bx1 = bcx + 0.5f * bw, by1 = bcy + 0.5f * bh;
        float area2 = (bx1 - bx0) * (by1 - by0);
        float iw = fmaxf(fminf(ax1, bx1) - fmaxf(ax0, bx0), 0.0f);
        float ih = fmaxf(fminf(ay1, by1) - fmaxf(ay0, by0), 0.0f);
        float inter = iw * ih;
        float uni = area1 + area2 - inter;
        float iou = inter / uni;
        float cw = fmaxf(fmaxf(ax1, bx1) - fminf(ax0, bx0), 0.0f);
        float ch = fmaxf(fmaxf(ay1, by1) - fminf(ay0, by0), 0.0f);
        float ac = cw * ch;
        float giou = iou - (ac - uni) / ac;
        float l1c = fabsf(cx - bcx) + fabsf(cy - bcy) + fabsf(w - bw) + fabsf(h - bh);
        float prob = (s_lab[m] == 0) ? p0 : p1;
        s_cost[m * NP + n] = -2.0f * prob + 5.0f * l1c - 2.0f * giou;
    }
    __syncthreads();

    // ---- phase 2: Jonker-Volgenant, warp 0 only (barrier-free) ----
    if (tid < 32) {
        const double DINF = 1e300;
        const int lane = tid;
        const unsigned FULL = 0xFFFFFFFFu;

        #pragma unroll
        for (int k = 0; k < 10; ++k) {
            int j = 1 + lane + 32 * k;
            if (j <= NP) { s_v[j] = 0.0; s_p[j] = 0; }
        }
        s_u[lane] = 0.0;
        if (lane == 0) { s_u[32] = 0.0; s_p[0] = 0; s_v[0] = 0.0; }
        __syncwarp();

        for (int i = 1; i <= MT; ++i) {
            if (lane == 0) { s_p[0] = (short)i; s_used[0] = 0; }
            #pragma unroll
            for (int k = 0; k < 10; ++k) {
                int j = 1 + lane + 32 * k;
                if (j <= NP) { s_minv[j] = DINF; s_used[j] = 0; }
            }
            __syncwarp();
            int j0 = 0;
            while (true) {
                if (lane == 0) s_used[j0] = 1;
                __syncwarp();
                int i0 = (int)s_p[j0];
                double ui0 = s_u[i0];
                const float* crow = s_cost + (i0 - 1) * NP;
                double best = DINF;
                int bidx = NP + 1;
                #pragma unroll
                for (int k = 0; k < 10; ++k) {
                    int j = 1 + lane + 32 * k;
                    if (j <= NP && !s_used[j]) {
                        double cur = (double)crow[j - 1] - ui0 - s_v[j];
                        double mv = s_minv[j];
                        if (cur < mv) { mv = cur; s_minv[j] = cur; s_way[j] = (short)j0; }
                        if (mv < best) { best = mv; bidx = j; } // ascending j within lane
                    }
                }
                // warp argmin (value, then smaller column index)
                #pragma unroll
                for (int off = 16; off; off >>= 1) {
                    double ov = __shfl_down_sync(FULL, best, off);
                    int    oi = __shfl_down_sync(FULL, bidx, off);
                    if (ov < best || (ov == best && oi < bidx)) { best = ov; bidx = oi; }
                }
                double delta = __shfl_sync(FULL, best, 0);
                int    j1    = __shfl_sync(FULL, bidx, 0);
                // update potentials / minv
                #pragma unroll
                for (int k = 0; k < 10; ++k) {
                    int j = 1 + lane + 32 * k;
                    if (j <= NP) {
                        if (s_used[j]) { s_u[(int)s_p[j]] += delta; s_v[j] -= delta; }
                        else           s_minv[j] -= delta;
                    }
                }
                if (lane == 0) s_u[(int)s_p[0]] += delta;   // column 0 (virtual)
                __syncwarp();
                j0 = j1;
                if (s_p[j0] == 0) break;
            }
            if (lane == 0) {
                int jj = j0;
                while (jj) { int jn = (int)s_way[jj]; s_p[jj] = s_p[jn]; jj = jn; }
            }
            __syncwarp();
        }
        #pragma unroll
        for (int k = 0; k < 10; ++k) {
            int j = 1 + lane + 32 * k;
            if (j <= NP && s_p[j] > 0) s_pidx[(int)s_p[j] - 1] = j - 1;
        }
    }
    __syncthreads();

    // ---- phase 3: loss partials (warp m handles target m) ----
    {
        int wid = tid >> 5, lane = tid & 31;
        int m = wid;
        int idx = s_pidx[m];
        const float* row = il + ((size_t)(f * NP + idx)) * KID;
        float x[16];
        float mx = -INFINITY;
        #pragma unroll
        for (int k = 0; k < 16; ++k) { x[k] = row[lane + 32 * k]; mx = fmaxf(mx, x[k]); }
        #pragma unroll
        for (int off = 16; off; off >>= 1) mx = fmaxf(mx, __shfl_xor_sync(0xFFFFFFFFu, mx, off));
        float se = 0.0f;
        #pragma unroll
        for (int k = 0; k < 16; ++k) se += __expf(x[k] - mx);
        #pragma unroll
        for (int off = 16; off; off >>= 1) se += __shfl_xor_sync(0xFFFFFFFFu, se, off);

        if (lane == 0) {
            int t = tids[f * MT + m];
            s_nll[m] = (mx + __logf(se)) - row[t];

            float cx = pb[(f * NP + idx) * 4 + 0];
            float cy = pb[(f * NP + idx) * 4 + 1];
            float w  = pb[(f * NP + idx) * 4 + 2];
            float h  = pb[(f * NP + idx) * 4 + 3];
            float bcx = s_tb[m][0], bcy = s_tb[m][1], bw = s_tb[m][2], bh = s_tb[m][3];
            s_l1[m] = fabsf(cx - bcx) + fabsf(cy - bcy) + fabsf(w - bw) + fabsf(h - bh);

            float ax0 = cx - 0.5f * w, ay0 = cy - 0.5f * h;
            float ax1 = cx + 0.5f * w, ay1 = cy + 0.5f * h;
            float bx0 = bcx - 0.5f * bw, by0 = bcy - 0.5f * bh;
            float bx1 = bcx + 0.5f * bw, by1 = bcy + 0.5f * bh;
            float area1 = (ax1 - ax0) * (ay1 - ay0);
            float area2 = (bx1 - bx0) * (by1 - by0);
            float iw = fmaxf(fminf(ax1, bx1) - fmaxf(ax0, bx0), 0.0f);
            float ih = fmaxf(fminf(ay1, by1) - fmaxf(ay0, by0), 0.0f);
            float inter = iw * ih;
            float uni = area1 + area2 - inter;
            float iou = inter / uni;
            float cw = fmaxf(fmaxf(ax1, bx1) - fminf(ax0, bx0), 0.0f);
            float ch = fmaxf(fmaxf(ay1, by1) - fminf(ay0, by0), 0.0f);
            float ac = cw * ch;
            s_g[m] = iou - (ac - uni) / ac;
        }
    }
    __syncthreads();
    if (tid == 0) {
        double a = 0.0, b = 0.0, c = 0.0;
        #pragma unroll
        for (int k = 0; k < MT; ++k) {
            a += (double)s_l1[k]; b += (double)s_g[k]; c += (double)s_nll[k];
        }
        g_part[f * 3 + 0] = a;
        g_part[f * 3 + 1] = b;
        g_part[f * 3 + 2] = c;
    }
}

// ============================================================
// Final reduction: 128 threads, deterministic shuffle tree.
// ============================================================
__global__ void final_kernel(float* __restrict__ out) {
    int tid = threadIdx.x;              // 128 threads, one per frame
    double a = g_part[tid * 3 + 0];
    double b = g_part[tid * 3 + 1];
    double c = g_part[tid * 3 + 2];
    #pragma unroll
    for (int off = 16; off; off >>= 1) {
        a += __shfl_down_sync(0xFFFFFFFFu, a, off);
        b += __shfl_down_sync(0xFFFFFFFFu, b, off);
        c += __shfl_down_sync(0xFFFFFFFFu, c, off);
    }
    __shared__ double sa[4], sb[4], sc[4];
    int wid = tid >> 5;
    if ((tid & 31) == 0) { sa[wid] = a; sb[wid] = b; sc[wid] = c; }
    __syncthreads();
    if (tid == 0) {
        double A = sa[0] + sa[1] + sa[2] + sa[3];
        double B = sb[0] + sb[1] + sb[2] + sb[3];
        double Cc = sc[0] + sc[1] + sc[2] + sc[3];
        double loss_l1   = A / (double)(FF * MT * 4);
        double loss_giou = 1.0 - B / (double)(FF * MT);
        double loss_id   = Cc / (double)(FF * MT);
        double loss = 5.0 * loss_l1 + 2.0 * loss_giou + 1.0 * loss_id;
        out[0] = (float)loss;
        out[1] = 0.0f;
        out[2] = (float)loss_l1;
        out[3] = (float)loss_giou;
        out[4] = (float)loss_id;
    }
}

extern "C" void kernel_launch(void* const* d_in, const int* in_sizes, int n_in,
                              void* d_out, int out_size) {
    const float* pred_logits   = (const float*)d_in[0];   // [8,16,300,2]
    const float* pred_boxes    = (const float*)d_in[1];   // [8,16,300,4]
    const float* id_logits     = (const float*)d_in[2];   // [8,16,300,512]
    const int*   target_labels = (const int*)  d_in[3];   // [128,32]
    const float* target_boxes  = (const float*)d_in[4];   // [128,32,4]
    const int*   target_ids    = (const int*)  d_in[5];   // [128,32]
    float* out = (float*)d_out;

    fused_kernel<<<FF, 1024>>>(pred_logits, pred_boxes, id_logits,
                               target_labels, target_boxes, target_ids);
    final_kernel<<<1, 128>>>(out);
}